// round 13
// baseline (speedup 1.0000x reference)
#include <cuda_runtime.h>
#include <cstdint>

// Problem shape (fixed by reference): B=32, S=128, V=32000
// loss = -sum_{b,s} prob[b,s,target[b,s]] * reward[b]
//
// Latency-bound: 4096 scattered gathers -> 1 scalar. Model (R2-R12, A/A
// confirmed): kernel = ~5us fixed launch/ramp/drain + ~0.5us cold gather
// wave + tail; identical sources draw +-0.3us. Best measured halves:
//   R2  (5.41us kernel): NO intra-CTA combine — 128 raw per-warp atomics
//   R8/R12 (5.47-5.73):  single packed 64-bit atomic rendezvous, 1 node
// This round combines them: drop smem + __syncthreads entirely; each of
// the 128 warp leaders issues the packed atomic (fixed_sum<<32 | count),
// arrival target 128 (2^32 % 128 == 0 -> wrap-safe). The 128th arriver
// holds the complete total in-register -> STG -loss (overwrites poison),
// then exact integer reset off the critical path.

#define B_ 32
#define S_ 128
#define V_ 32000
#define N_ (B_ * S_)      // 4096
#define NCTA_ 32
#define NTHR_ 128
#define NWARPS_ (NCTA_ * NTHR_ / 32)      // 128 arrivals
#define FIX_SCALE 1048576.0f              // 2^20
#define FIX_INV  (-9.5367431640625e-07f)  // -(2^-20), fused negate

__device__ unsigned long long g_acc = 0ULL;  // (fixed_sum<<32) | arrival_count

__global__ void __launch_bounds__(NTHR_, 1)
rl_loss_kernel(const float* __restrict__ prob,
               const int* __restrict__ target,
               const float* __restrict__ reward,
               float* __restrict__ out) {
    int i = blockIdx.x * NTHR_ + threadIdx.x;   // 0..4095
    float r = __ldg(&reward[i >> 7]);           // independent; issues first
    int t = __ldg(&target[i]);                  // coalesced int32
    // 32-bit index: max = 4095*32000 + 31999 = 131,071,999 < 2^31
    float v = __ldg(&prob[i * V_ + t]);         // scattered gather
    float x = v * r;

    // warp tree-reduce (5 shuffles)
    #pragma unroll
    for (int off = 16; off > 0; off >>= 1)
        x += __shfl_xor_sync(0xFFFFFFFFu, x, off);

    if ((threadIdx.x & 31) == 0) {
        // Quantize warp partial (x in [0,32)) to fixed-point: < 2^25.
        // Grand total ~2^30 < 2^32 — no overflow into the count field's
        // carry space... (sum occupies high 32 bits exclusively).
        unsigned int fx = (unsigned int)__float2uint_rn(x * FIX_SCALE);
        unsigned long long pack = ((unsigned long long)fx << 32) | 1ULL;

        // Single relaxed atomic carries both sum and arrival count.
        unsigned long long old = atomicAdd(&g_acc, pack);

        if ((old & 0xFFFFFFFFULL) == (unsigned long long)(NWARPS_ - 1)) {
            unsigned long long total = old + pack;   // complete, in-register
            unsigned int fixed_tot = (unsigned int)(total >> 32);
            *out = (float)fixed_tot * FIX_INV;       // -sum; overwrites poison
            // Exact integer reset to 0 for next replay (off critical path;
            // committed by the kernel-boundary fence before the next launch).
            atomicAdd(&g_acc, (unsigned long long)(0ULL - total));
        }
    }
}

extern "C" void kernel_launch(void* const* d_in, const int* in_sizes, int n_in,
                              void* d_out, int out_size) {
    // Identify inputs by element count, robust to ordering:
    //   prob: B*S*V = 131,072,000   target: B*S = 4096   reward: B = 32
    const float* prob   = nullptr;
    const int*   target = nullptr;
    const float* reward = nullptr;
    for (int k = 0; k < n_in; k++) {
        if (in_sizes[k] == N_ * V_)      prob   = (const float*)d_in[k];
        else if (in_sizes[k] == N_)      target = (const int*)d_in[k];
        else if (in_sizes[k] == B_)      reward = (const float*)d_in[k];
    }
    float* out = (float*)d_out;

    // Single graph node: 32 CTAs x 128 threads, one gather each.
    rl_loss_kernel<<<NCTA_, NTHR_>>>(prob, target, reward, out);
}

// round 16
// speedup vs baseline: 1.0591x; 1.0591x over previous
#include <cuda_runtime.h>
#include <cstdint>

// Problem shape (fixed by reference): B=32, S=128, V=32000
// loss = -sum_{b,s} prob[b,s,target[b,s]] * reward[b]
//
// Latency-bound: 4096 scattered gathers -> 1 scalar. Final model (R2-R13):
// kernel = ~5us fixed launch/ramp/drain + gather wave + tail; identical
// sources draw +-0.3us. All structural axes tested; this source is the
// best-validated point (total 6.624 on both prior runs; best kernel 5.47).
// R13 (no smem combine, 128-wide atomic stream) measured worse — discarded.
//
// Design: 32 CTAs x 128 thr, one gather/thread, 32-bit gather index,
// warp shuffle reduce + smem combine, single packed 64-bit relaxed
// atomicAdd rendezvous (fixed_sum<<32 | arrival_count) — the 32nd arriver
// holds the complete total in-register from the atomic return, STGs -loss
// (overwrites harness poison), then exact integer reset off the critical
// path (committed by the kernel-boundary fence before the next replay).

#define B_ 32
#define S_ 128
#define V_ 32000
#define N_ (B_ * S_)      // 4096
#define NCTA_ 32
#define NTHR_ 128
#define FIX_SCALE 1048576.0f              // 2^20
#define FIX_INV  (-9.5367431640625e-07f)  // -(2^-20), fused negate

__device__ unsigned long long g_acc = 0ULL;  // (fixed_sum<<32) | arrival_count

__global__ void __launch_bounds__(NTHR_, 1)
rl_loss_kernel(const float* __restrict__ prob,
               const int* __restrict__ target,
               const float* __restrict__ reward,
               float* __restrict__ out) {
    __shared__ float s_warp[NTHR_ / 32];

    int i = blockIdx.x * NTHR_ + threadIdx.x;   // 0..4095
    float r = __ldg(&reward[i >> 7]);           // independent; issues first
    int t = __ldg(&target[i]);                  // coalesced int32
    // 32-bit index: max = 4095*32000 + 31999 = 131,071,999 < 2^31
    float v = __ldg(&prob[i * V_ + t]);         // scattered gather
    float x = v * r;

    // warp tree-reduce (5 shuffles)
    #pragma unroll
    for (int off = 16; off > 0; off >>= 1)
        x += __shfl_xor_sync(0xFFFFFFFFu, x, off);

    if ((threadIdx.x & 31) == 0) s_warp[threadIdx.x >> 5] = x;
    __syncthreads();

    if (threadIdx.x == 0) {
        float p = (s_warp[0] + s_warp[1]) + (s_warp[2] + s_warp[3]);

        // Quantize CTA partial (p in [0,128)) to fixed-point: < 2^27.
        unsigned int fx = (unsigned int)__float2uint_rn(p * FIX_SCALE);
        unsigned long long pack = ((unsigned long long)fx << 32) | 1ULL;

        // Single relaxed atomic carries both sum and arrival count.
        unsigned long long old = atomicAdd(&g_acc, pack);

        if ((old & 0xFFFFFFFFULL) == (unsigned long long)(NCTA_ - 1)) {
            unsigned long long total = old + pack;   // complete, in-register
            unsigned int fixed_tot = (unsigned int)(total >> 32);
            *out = (float)fixed_tot * FIX_INV;       // -sum; overwrites poison
            // Exact integer reset to 0 for next replay (off critical path;
            // committed by the kernel-boundary fence before the next launch).
            atomicAdd(&g_acc, (unsigned long long)(0ULL - total));
        }
    }
}

extern "C" void kernel_launch(void* const* d_in, const int* in_sizes, int n_in,
                              void* d_out, int out_size) {
    // Identify inputs by element count, robust to ordering:
    //   prob: B*S*V = 131,072,000   target: B*S = 4096   reward: B = 32
    const float* prob   = nullptr;
    const int*   target = nullptr;
    const float* reward = nullptr;
    for (int k = 0; k < n_in; k++) {
        if (in_sizes[k] == N_ * V_)      prob   = (const float*)d_in[k];
        else if (in_sizes[k] == N_)      target = (const int*)d_in[k];
        else if (in_sizes[k] == B_)      reward = (const float*)d_in[k];
    }
    float* out = (float*)d_out;

    // Single graph node: 32 CTAs x 128 threads, one gather each.
    rl_loss_kernel<<<NCTA_, NTHR_>>>(prob, target, reward, out);
}